// round 14
// baseline (speedup 1.0000x reference)
#include <cuda_runtime.h>

// Problem constants (fixed by the reference)
#define Lr    512
#define LMASK (Lr - 1)
#define Bb    16
#define Cc    4
#define NLAY  4
#define HIDN  256
#define HROWS 32              // output rows per CTA
#define TROWS 48              // tile rows = HROWS + 2*8 halo
#define NBLK  (Lr / HROWS)    // 16 row blocks
#define TPB   256             // threads per CTA (each owns a column pair)

#define KTOT   (Cc * Lr)      // 2048
#define KCHUNK 16
#define NKC    (KTOT / KCHUNK)   // 128 k-chunks
#define BGRP   2                 // batch groups
#define BSUB   (Bb / BGRP)       // 8 batches per mlp CTA

#define W1_F4      (KTOT * HIDN / 4)   // 131072 float4 in W1
#define NPREFETCH  (NBLK * Bb * (Cc - 1))  // 768 prefetch CTAs (fast path)

typedef unsigned long long u64;

// Per-block partial diagonal sums: [b][c][blk][r].
__device__ float g_part[Bb * Cc * NBLK * Lr];
// MLP hidden accumulator [b][t] (atomic) + completion ticket.
__device__ float g_hacc[Bb * HIDN];
__device__ int   g_ctr;
// Prefetch sink (never read; defeats DCE).
__device__ float g_pfsink[NPREFETCH];

__device__ __forceinline__ float celu_f(float v) {
    return v > 0.f ? v : (__expf(v) - 1.f);
}

// Inline weight-equality test (warp 0 -> shared flag).
__device__ __forceinline__ void weights_shared_check(
    const float* __restrict__ w_self, const float* __restrict__ w_nbr,
    int tid, int* s_flag)
{
    if (tid < 32) {
        bool eq = true;
        #pragma unroll
        for (int c = 1; c < Cc; ++c) {
            if (tid < NLAY)     eq &= (w_self[c * NLAY + tid] == w_self[tid]);
            if (tid < NLAY * 2) eq &= (w_nbr[c * NLAY * 2 + tid] == w_nbr[tid]);
        }
        unsigned m = __ballot_sync(0xffffffffu, eq);
        if (tid == 0) *s_flag = (m == 0xffffffffu) ? 1 : 0;
    }
}

// ---- packed f32x2 helpers ----
__device__ __forceinline__ u64 add2(u64 a, u64 b) {
    u64 r; asm("add.rn.f32x2 %0, %1, %2;" : "=l"(r) : "l"(a), "l"(b)); return r;
}
__device__ __forceinline__ u64 mul2(u64 a, u64 b) {
    u64 r; asm("mul.rn.f32x2 %0, %1, %2;" : "=l"(r) : "l"(a), "l"(b)); return r;
}
__device__ __forceinline__ u64 fma2(u64 a, u64 b, u64 c) {
    u64 r; asm("fma.rn.f32x2 %0, %1, %2, %3;" : "=l"(r) : "l"(a), "l"(b), "l"(c)); return r;
}
__device__ __forceinline__ void unpk(u64 v, float& a, float& b) {
    asm("mov.b64 {%0, %1}, %2;" : "=f"(a), "=f"(b) : "l"(v));
}
__device__ __forceinline__ u64 pk2(float a, float b) {
    u64 r; asm("mov.b64 %0, {%1, %2};" : "=l"(r) : "f"(a), "f"(b)); return r;
}

// Dynamic smem: buf [TROWS*Lr] | nsx|nsy|nsz [Lr each] -> 104448 bytes
#define SMEM_FLOATS (TROWS * Lr + 3 * Lr)
extern __shared__ float s_mem[];

#define STEP2(u, DO_STORE) { \
    u64 vp2 = *(const u64*)(colp + ((u) + 2) * TPB); \
    u64 hl  = *(const u64*)(lftp + (u) * TPB); \
    u64 hr  = *(const u64*)(rgtp + (u) * TPB); \
    u64 vm2 = W[(lo + (u) + 2) & 3]; \
    u64 vm1 = W[(lo + (u) + 3) & 3]; \
    u64 v0  = W[(lo + (u)    ) & 3]; \
    u64 vp1 = W[(lo + (u) + 1) & 3]; \
    u64 t1  = add2(vm1, vp1); \
    u64 t2  = add2(add2(vm2, vp2), add2(hl, hr)); \
    u64 ypk = fma2(wn12, t2, mul2(ws2, v0)); \
    float t1x, t1y, hlx, hly, hrx, hry, v0x, v0y, yx, yy; \
    unpk(t1, t1x, t1y); unpk(hl, hlx, hly); unpk(hr, hrx, hry); \
    unpk(v0, v0x, v0y); unpk(ypk, yx, yy); \
    float y0 = fmaf(wn0, t1x + (hly + v0y), yx); \
    float y1 = fmaf(wn0, t1y + (v0x + hrx), yy); \
    float nv0 = v0x + celu_f(y0); \
    float nv1 = v0y + celu_f(y1); \
    { int gr = (grp + (u)) & LMASK; \
      nv0 = (gr == c0) ? 0.f : nv0; \
      nv1 = (gr == c1) ? 0.f : nv1; } \
    if (DO_STORE) *(u64*)(colp + ((u) - 4) * TPB) = Q[(lo + (u)) & 3]; \
    Q[(lo + (u)) & 3] = pk2(nv0, nv1); \
    W[(lo + (u) + 2) & 3] = vp2; \
}

// Grid: (NBLK, Bb, Cc) — channel slowest so the 256 working CTAs (c==0 on
// the shared-weight fast path) are launch-order bids 0..255. The 768 c>0
// CTAs on the fast path prefetch W1 into L2 (overlapped with the stencil),
// so mlp_kernel's W1 sweep hits L2 instead of cold DRAM.
__global__ __launch_bounds__(TPB, 2)
void fused_layers_kernel(const float* __restrict__ n,
                         const float* __restrict__ w_self,
                         const float* __restrict__ w_nbr,
                         const float* __restrict__ W1)
{
    const int blk = blockIdx.x;
    const int b   = blockIdx.y;
    const int c   = blockIdx.z;
    __shared__ int s_flag;

    // Reset the MLP accumulator + ticket for this call (before mlp_kernel runs).
    if (blk == 0 && c == 0) {
        g_hacc[b * HIDN + threadIdx.x] = 0.f;
        if (b == 0 && threadIdx.x == 0) g_ctr = 0;
    }

    // Shared-weight CSE: if all channels have identical weights, channel-0
    // CTAs produce every channel's result; c>0 CTAs prefetch W1 then exit.
    if (c != 0) {
        weights_shared_check(w_self, w_nbr, threadIdx.x, &s_flag);
        __syncthreads();
        if (s_flag) {
            const int pid = (c - 1) * (NBLK * Bb) + b * NBLK + blk;  // 0..767
            const float4* W14 = reinterpret_cast<const float4*>(W1);
            float s = 0.f;
            for (int idx = pid * TPB + threadIdx.x; idx < W1_F4;
                 idx += NPREFETCH * TPB) {
                float4 v = W14[idx];                  // fills L2
                s += v.x + v.y + v.z + v.w;
            }
            // warp-reduce + one store per warp so loads can't be DCE'd
            #pragma unroll
            for (int off = 16; off > 0; off >>= 1)
                s += __shfl_down_sync(0xffffffffu, s, off);
            if ((threadIdx.x & 31) == 0 && threadIdx.x < 32)
                g_pfsink[pid] = s;
            return;
        }
    }

    const int j2 = threadIdx.x;           // column pair index 0..255

    float*  buf  = s_mem;
    float2* buf2 = reinterpret_cast<float2*>(s_mem);   // [TROWS][TPB]
    float*  nsx  = s_mem + TROWS * Lr;
    float*  nsy  = nsx + Lr;
    float*  nsz  = nsx + 2 * Lr;

    {
        const float* base = n + (size_t)b * Lr * 3;
        for (int k = j2; k < Lr; k += TPB) {
            nsx[k] = base[3 * k + 0];
            nsy[k] = base[3 * k + 1];
            nsz[k] = base[3 * k + 2];
        }
    }
    __syncthreads();

    const int c0 = 2 * j2, c1 = c0 + 1;
    const int r0 = blk * HROWS - 8;       // global row of tile row 0 (mod 512)

    // Layer-0 input (masked Gram) directly in smem.
    {
        const float ax = nsx[c0], ay = nsy[c0], az = nsz[c0];
        const float bx = nsx[c1], by = nsy[c1], bz = nsz[c1];
        #pragma unroll 4
        for (int t = 0; t < TROWS; ++t) {
            int gr = (r0 + t) & LMASK;
            float px = nsx[gr], py = nsy[gr], pz = nsz[gr];
            float g0 = ax * px + ay * py + az * pz;
            float g1 = bx * px + by * py + bz * pz;
            g0 = (gr == c0) ? 0.f : g0;
            g1 = (gr == c1) ? 0.f : g1;
            buf2[t * TPB + j2] = make_float2(g0, g1);
        }
    }
    __syncthreads();

    const int jm = (j2 - 1) & (TPB - 1);
    const int jp = (j2 + 1) & (TPB - 1);

    #pragma unroll
    for (int ell = 0; ell < NLAY; ++ell) {
        const float ws  = w_self[c * NLAY + ell];
        const float wn0 = w_nbr[(c * NLAY + ell) * 2 + 0];
        const float wn1 = w_nbr[(c * NLAY + ell) * 2 + 1];
        const u64 ws2  = pk2(ws, ws);
        const u64 wn12 = pk2(wn1, wn1);
        const int lo = 2 + 2 * ell;
        const int hi = 45 - 2 * ell;
        const int ngroups = (hi - lo + 1) >> 2;        // 11,10,9,8

        u64 W[4], Q[4];
        W[(lo - 2) & 3] = *(const u64*)(buf2 + (lo - 2) * TPB + j2);
        W[(lo - 1) & 3] = *(const u64*)(buf2 + (lo - 1) * TPB + j2);
        W[(lo    ) & 3] = *(const u64*)(buf2 + (lo    ) * TPB + j2);
        W[(lo + 1) & 3] = *(const u64*)(buf2 + (lo + 1) * TPB + j2);

        float2* colp = buf2 + lo * TPB + j2;
        float2* lftp = buf2 + lo * TPB + jm;
        float2* rgtp = buf2 + lo * TPB + jp;
        int grp = r0 + lo;

        STEP2(0, 0) STEP2(1, 0) STEP2(2, 0) STEP2(3, 0)
        __syncthreads();
        colp += 4 * TPB; lftp += 4 * TPB; rgtp += 4 * TPB; grp += 4;

        for (int g = 1; g < ngroups; ++g) {
            STEP2(0, 1) STEP2(1, 1) STEP2(2, 1) STEP2(3, 1)
            __syncthreads();
            colp += 4 * TPB; lftp += 4 * TPB; rgtp += 4 * TPB; grp += 4;
        }

        *(u64*)(colp - 4 * TPB) = Q[(hi - 3) & 3];
        *(u64*)(colp - 3 * TPB) = Q[(hi - 2) & 3];
        *(u64*)(colp - 2 * TPB) = Q[(hi - 1) & 3];
        *(u64*)(colp - 1 * TPB) = Q[(hi    ) & 3];
        __syncthreads();
    }

    // sep partial: thread owns r = c0 and r = c1; sum this block's 32 rows.
    float acc0 = 0.f, acc1 = 0.f;
    #pragma unroll 8
    for (int t = 8; t < 8 + HROWS; ++t) {
        int gr = r0 + t;
        acc0 += buf[t * Lr + ((gr + c0) & LMASK)];
        acc1 += buf[t * Lr + ((gr + c1) & LMASK)];
    }
    float2* outp = reinterpret_cast<float2*>(
        &g_part[(((size_t)b * Cc + c) * NBLK + blk) * Lr + c0]);
    *outp = make_float2(acc0, acc1);
}

// ---- MLP kernel: 128 k-chunks x 2 batch-groups = 256 CTAs.
//      Each CTA: 16-k x 8-batch GEMM slice -> 8 atomics/thread;
//      ticketed last CTA computes the head for all batches. ----
__global__ __launch_bounds__(256, 4)
void mlp_kernel(const float* __restrict__ W1,
                const float* __restrict__ w_self,
                const float* __restrict__ w_nbr,
                const float* __restrict__ b1,
                const float* __restrict__ W2,
                const float* __restrict__ b2,
                float* __restrict__ out)
{
    __shared__ float ssep[BSUB][KCHUNK];   // 8 x 16
    __shared__ int s_flag, s_last;
    const int kc = blockIdx.x, bg = blockIdx.y, t = threadIdx.x;
    const int b0 = bg * BSUB;

    weights_shared_check(w_self, w_nbr, t, &s_flag);
    __syncthreads();
    const int wf = s_flag;

    // Build sep chunk for this batch subgroup: 128 entries, 1 per thread.
    if (t < BSUB * KCHUNK) {
        const int bb = t >> 4, kk = t & (KCHUNK - 1);
        const int k  = kc * KCHUNK + kk;
        const int cc = wf ? 0 : (k >> 9);          // shared-weight fast path
        const int r  = k & LMASK;
        const float* p = &g_part[(((size_t)(b0 + bb) * Cc + cc) * NBLK) * Lr + r];
        float ssum = 0.f;
        #pragma unroll
        for (int q = 0; q < NBLK; ++q) ssum += p[q * Lr];
        ssep[bb][kk] = ssum;
    }
    __syncthreads();

    float acc[BSUB];
    #pragma unroll
    for (int bb = 0; bb < BSUB; ++bb) acc[bb] = 0.f;

    #pragma unroll
    for (int kk = 0; kk < KCHUNK; ++kk) {
        float w = W1[(size_t)(kc * KCHUNK + kk) * HIDN + t];   // L2-warm now
        #pragma unroll
        for (int bb = 0; bb < BSUB; ++bb)
            acc[bb] = fmaf(ssep[bb][kk], w, acc[bb]);
    }

    // Accumulate hidden pre-activations atomically.
    #pragma unroll
    for (int bb = 0; bb < BSUB; ++bb)
        atomicAdd(&g_hacc[(b0 + bb) * HIDN + t], acc[bb]);

    // Last CTA finishes the head for all batches.
    __threadfence();
    if (t == 0) s_last = (atomicAdd(&g_ctr, 1) == NKC * BGRP - 1);
    __syncthreads();
    if (!s_last) return;

    const int wid = t >> 5, lane = t & 31;        // warp wid -> batches 2w, 2w+1
    #pragma unroll
    for (int rep = 0; rep < 2; ++rep) {
        const int bb = 2 * wid + rep;
        float sum = 0.f;
        #pragma unroll
        for (int i = 0; i < 8; ++i) {
            int col = lane + 32 * i;
            float h = __ldcg(&g_hacc[bb * HIDN + col]) + b1[col];
            sum += celu_f(h) * W2[col];
        }
        #pragma unroll
        for (int off = 16; off > 0; off >>= 1)
            sum += __shfl_down_sync(0xffffffffu, sum, off);
        if (lane == 0) out[bb] = __expf(-(sum + b2[0]));
    }
}

extern "C" void kernel_launch(void* const* d_in, const int* in_sizes, int n_in,
                              void* d_out, int out_size)
{
    const float* n      = (const float*)d_in[0];
    const float* w_self = (const float*)d_in[1];
    const float* w_nbr  = (const float*)d_in[2];
    const float* W1     = (const float*)d_in[3];
    const float* b1     = (const float*)d_in[4];
    const float* W2     = (const float*)d_in[5];
    const float* b2     = (const float*)d_in[6];
    float* out = (float*)d_out;

    const size_t smem_bytes = SMEM_FLOATS * sizeof(float);   // 104448 B
    cudaFuncSetAttribute(fused_layers_kernel,
                         cudaFuncAttributeMaxDynamicSharedMemorySize,
                         (int)smem_bytes);

    dim3 grid(NBLK, Bb, Cc);   // 1024 CTAs; actives (c==0) are bids 0..255
    fused_layers_kernel<<<grid, TPB, smem_bytes>>>(n, w_self, w_nbr, W1);

    mlp_kernel<<<dim3(NKC, BGRP), 256>>>(W1, w_self, w_nbr, b1, W2, b2, out);
}

// round 15
// speedup vs baseline: 1.0943x; 1.0943x over previous
#include <cuda_runtime.h>

// Problem constants (fixed by the reference)
#define Lr    512
#define LMASK (Lr - 1)
#define Bb    16
#define Cc    4
#define NLAY  4
#define HIDN  256
#define HROWS 32              // output rows per CTA
#define TROWS 48              // tile rows = HROWS + 2*8 halo
#define NBLK  (Lr / HROWS)    // 16 row blocks
#define TPB   256             // threads per CTA (each owns a column pair)

#define KTOT   (Cc * Lr)      // 2048
#define NRC    32             // mlp r-chunk CTAs (x)
#define MBG    4              // mlp batch groups (y)
#define MBSUB  (Bb / MBG)     // 4 batches per mlp CTA
#define NMLP   (NRC * MBG)    // 128 mlp CTAs

typedef unsigned long long u64;

// Per-block partial diagonal sums: [b][c][blk][r].
__device__ float g_part[Bb * Cc * NBLK * Lr];
// Channel-folded W1 (fast path): W1sum[r][t] = sum_c W1[c*512+r][t].
__device__ float g_W1sum[Lr * HIDN];
// MLP hidden accumulator [b][t] (atomic) + completion ticket.
__device__ float g_hacc[Bb * HIDN];
__device__ int   g_ctr;

__device__ __forceinline__ float celu_f(float v) {
    return v > 0.f ? v : (__expf(v) - 1.f);
}

// Inline weight-equality test (warp 0 -> shared flag).
__device__ __forceinline__ void weights_shared_check(
    const float* __restrict__ w_self, const float* __restrict__ w_nbr,
    int tid, int* s_flag)
{
    if (tid < 32) {
        bool eq = true;
        #pragma unroll
        for (int c = 1; c < Cc; ++c) {
            if (tid < NLAY)     eq &= (w_self[c * NLAY + tid] == w_self[tid]);
            if (tid < NLAY * 2) eq &= (w_nbr[c * NLAY * 2 + tid] == w_nbr[tid]);
        }
        unsigned m = __ballot_sync(0xffffffffu, eq);
        if (tid == 0) *s_flag = (m == 0xffffffffu) ? 1 : 0;
    }
}

// ---- packed f32x2 helpers ----
__device__ __forceinline__ u64 add2(u64 a, u64 b) {
    u64 r; asm("add.rn.f32x2 %0, %1, %2;" : "=l"(r) : "l"(a), "l"(b)); return r;
}
__device__ __forceinline__ u64 mul2(u64 a, u64 b) {
    u64 r; asm("mul.rn.f32x2 %0, %1, %2;" : "=l"(r) : "l"(a), "l"(b)); return r;
}
__device__ __forceinline__ u64 fma2(u64 a, u64 b, u64 c) {
    u64 r; asm("fma.rn.f32x2 %0, %1, %2, %3;" : "=l"(r) : "l"(a), "l"(b), "l"(c)); return r;
}
__device__ __forceinline__ void unpk(u64 v, float& a, float& b) {
    asm("mov.b64 {%0, %1}, %2;" : "=f"(a), "=f"(b) : "l"(v));
}
__device__ __forceinline__ u64 pk2(float a, float b) {
    u64 r; asm("mov.b64 %0, {%1, %2};" : "=l"(r) : "f"(a), "f"(b)); return r;
}

// Dynamic smem: buf [TROWS*Lr] | nsx|nsy|nsz [Lr each] -> 104448 bytes
#define SMEM_FLOATS (TROWS * Lr + 3 * Lr)
extern __shared__ float s_mem[];

#define STEP2(u, DO_STORE) { \
    u64 vp2 = *(const u64*)(colp + ((u) + 2) * TPB); \
    u64 hl  = *(const u64*)(lftp + (u) * TPB); \
    u64 hr  = *(const u64*)(rgtp + (u) * TPB); \
    u64 vm2 = W[(lo + (u) + 2) & 3]; \
    u64 vm1 = W[(lo + (u) + 3) & 3]; \
    u64 v0  = W[(lo + (u)    ) & 3]; \
    u64 vp1 = W[(lo + (u) + 1) & 3]; \
    u64 t1  = add2(vm1, vp1); \
    u64 t2  = add2(add2(vm2, vp2), add2(hl, hr)); \
    u64 ypk = fma2(wn12, t2, mul2(ws2, v0)); \
    float t1x, t1y, hlx, hly, hrx, hry, v0x, v0y, yx, yy; \
    unpk(t1, t1x, t1y); unpk(hl, hlx, hly); unpk(hr, hrx, hry); \
    unpk(v0, v0x, v0y); unpk(ypk, yx, yy); \
    float y0 = fmaf(wn0, t1x + (hly + v0y), yx); \
    float y1 = fmaf(wn0, t1y + (v0x + hrx), yy); \
    float nv0 = v0x + celu_f(y0); \
    float nv1 = v0y + celu_f(y1); \
    { int gr = (grp + (u)) & LMASK; \
      nv0 = (gr == c0) ? 0.f : nv0; \
      nv1 = (gr == c1) ? 0.f : nv1; } \
    if (DO_STORE) *(u64*)(colp + ((u) - 4) * TPB) = Q[(lo + (u)) & 3]; \
    Q[(lo + (u)) & 3] = pk2(nv0, nv1); \
    W[(lo + (u) + 2) & 3] = vp2; \
}

// Grid: (NBLK, Bb, Cc) — channel slowest so the 256 working CTAs (c==0 on
// the shared-weight fast path) are launch-order bids 0..255. On the fast
// path the c>0 CTAs (pids 0..511) build g_W1sum (channel-folded W1) and
// exit — overlapped with the stencil, so mlp_kernel reads 512KB hot data.
__global__ __launch_bounds__(TPB, 2)
void fused_layers_kernel(const float* __restrict__ n,
                         const float* __restrict__ w_self,
                         const float* __restrict__ w_nbr,
                         const float* __restrict__ W1)
{
    const int blk = blockIdx.x;
    const int b   = blockIdx.y;
    const int c   = blockIdx.z;
    __shared__ int s_flag;

    // Reset the MLP accumulator + ticket for this call (before mlp_kernel runs).
    if (blk == 0 && c == 0) {
        g_hacc[b * HIDN + threadIdx.x] = 0.f;
        if (b == 0 && threadIdx.x == 0) g_ctr = 0;
    }

    if (c != 0) {
        weights_shared_check(w_self, w_nbr, threadIdx.x, &s_flag);
        __syncthreads();
        if (s_flag) {
            // Build W1sum: pid 0..511 cover all 512*256 outputs, 1 per thread.
            const int pid = (c - 1) * (NBLK * Bb) + b * NBLK + blk;  // 0..767
            const int idx = pid * TPB + threadIdx.x;
            if (idx < Lr * HIDN) {
                float s = 0.f;
                #pragma unroll
                for (int cc = 0; cc < Cc; ++cc)
                    s += W1[(size_t)cc * Lr * HIDN + idx];
                g_W1sum[idx] = s;
            }
            return;
        }
    }

    const int j2 = threadIdx.x;           // column pair index 0..255

    float*  buf  = s_mem;
    float2* buf2 = reinterpret_cast<float2*>(s_mem);   // [TROWS][TPB]
    float*  nsx  = s_mem + TROWS * Lr;
    float*  nsy  = nsx + Lr;
    float*  nsz  = nsx + 2 * Lr;

    {
        const float* base = n + (size_t)b * Lr * 3;
        for (int k = j2; k < Lr; k += TPB) {
            nsx[k] = base[3 * k + 0];
            nsy[k] = base[3 * k + 1];
            nsz[k] = base[3 * k + 2];
        }
    }
    __syncthreads();

    const int c0 = 2 * j2, c1 = c0 + 1;
    const int r0 = blk * HROWS - 8;       // global row of tile row 0 (mod 512)

    // Layer-0 input (masked Gram) directly in smem.
    {
        const float ax = nsx[c0], ay = nsy[c0], az = nsz[c0];
        const float bx = nsx[c1], by = nsy[c1], bz = nsz[c1];
        #pragma unroll 4
        for (int t = 0; t < TROWS; ++t) {
            int gr = (r0 + t) & LMASK;
            float px = nsx[gr], py = nsy[gr], pz = nsz[gr];
            float g0 = ax * px + ay * py + az * pz;
            float g1 = bx * px + by * py + bz * pz;
            g0 = (gr == c0) ? 0.f : g0;
            g1 = (gr == c1) ? 0.f : g1;
            buf2[t * TPB + j2] = make_float2(g0, g1);
        }
    }
    __syncthreads();

    const int jm = (j2 - 1) & (TPB - 1);
    const int jp = (j2 + 1) & (TPB - 1);

    #pragma unroll
    for (int ell = 0; ell < NLAY; ++ell) {
        const float ws  = w_self[c * NLAY + ell];
        const float wn0 = w_nbr[(c * NLAY + ell) * 2 + 0];
        const float wn1 = w_nbr[(c * NLAY + ell) * 2 + 1];
        const u64 ws2  = pk2(ws, ws);
        const u64 wn12 = pk2(wn1, wn1);
        const int lo = 2 + 2 * ell;
        const int hi = 45 - 2 * ell;
        const int ngroups = (hi - lo + 1) >> 2;        // 11,10,9,8

        u64 W[4], Q[4];
        W[(lo - 2) & 3] = *(const u64*)(buf2 + (lo - 2) * TPB + j2);
        W[(lo - 1) & 3] = *(const u64*)(buf2 + (lo - 1) * TPB + j2);
        W[(lo    ) & 3] = *(const u64*)(buf2 + (lo    ) * TPB + j2);
        W[(lo + 1) & 3] = *(const u64*)(buf2 + (lo + 1) * TPB + j2);

        float2* colp = buf2 + lo * TPB + j2;
        float2* lftp = buf2 + lo * TPB + jm;
        float2* rgtp = buf2 + lo * TPB + jp;
        int grp = r0 + lo;

        STEP2(0, 0) STEP2(1, 0) STEP2(2, 0) STEP2(3, 0)
        __syncthreads();
        colp += 4 * TPB; lftp += 4 * TPB; rgtp += 4 * TPB; grp += 4;

        for (int g = 1; g < ngroups; ++g) {
            STEP2(0, 1) STEP2(1, 1) STEP2(2, 1) STEP2(3, 1)
            __syncthreads();
            colp += 4 * TPB; lftp += 4 * TPB; rgtp += 4 * TPB; grp += 4;
        }

        *(u64*)(colp - 4 * TPB) = Q[(hi - 3) & 3];
        *(u64*)(colp - 3 * TPB) = Q[(hi - 2) & 3];
        *(u64*)(colp - 2 * TPB) = Q[(hi - 1) & 3];
        *(u64*)(colp - 1 * TPB) = Q[(hi    ) & 3];
        __syncthreads();
    }

    // sep partial: thread owns r = c0 and r = c1; sum this block's 32 rows.
    float acc0 = 0.f, acc1 = 0.f;
    #pragma unroll 8
    for (int t = 8; t < 8 + HROWS; ++t) {
        int gr = r0 + t;
        acc0 += buf[t * Lr + ((gr + c0) & LMASK)];
        acc1 += buf[t * Lr + ((gr + c1) & LMASK)];
    }
    float2* outp = reinterpret_cast<float2*>(
        &g_part[(((size_t)b * Cc + c) * NBLK + blk) * Lr + c0]);
    *outp = make_float2(acc0, acc1);
}

// ---- MLP kernel: 32 r-chunks x 4 batch-groups = 128 CTAs.
//      Fast path: 16-r x 4-batch slice vs g_W1sum (512KB, L2-hot) -> 4 atomics.
//      Slow path: 64-k x 4-batch slice vs full W1.
//      Ticketed last CTA computes the head for all batches. ----
__global__ __launch_bounds__(256, 4)
void mlp_kernel(const float* __restrict__ W1,
                const float* __restrict__ w_self,
                const float* __restrict__ w_nbr,
                const float* __restrict__ b1,
                const float* __restrict__ W2,
                const float* __restrict__ b2,
                float* __restrict__ out)
{
    __shared__ float ssep[MBSUB][64];
    __shared__ int s_flag, s_last;
    const int rc = blockIdx.x, bg = blockIdx.y, t = threadIdx.x;
    const int b0 = bg * MBSUB;

    weights_shared_check(w_self, w_nbr, t, &s_flag);
    __syncthreads();
    const int wf = s_flag;

    float acc[MBSUB];
    #pragma unroll
    for (int bb = 0; bb < MBSUB; ++bb) acc[bb] = 0.f;

    if (wf) {
        // sep chunk: 4 batches x 16 rows (channel 0), threads t<64.
        if (t < MBSUB * 16) {
            const int bb = t >> 4, kk = t & 15;
            const int r  = rc * 16 + kk;
            const float* p = &g_part[(((size_t)(b0 + bb) * Cc) * NBLK) * Lr + r];
            float ssum = 0.f;
            #pragma unroll
            for (int q = 0; q < NBLK; ++q) ssum += p[q * Lr];
            ssep[bb][kk] = ssum;
        }
        __syncthreads();

        #pragma unroll
        for (int kk = 0; kk < 16; ++kk) {
            float w = g_W1sum[(rc * 16 + kk) * HIDN + t];   // coalesced, hot
            #pragma unroll
            for (int bb = 0; bb < MBSUB; ++bb)
                acc[bb] = fmaf(ssep[bb][kk], w, acc[bb]);
        }
    } else {
        // sep chunk: 4 batches x 64 k (per-channel), threads t<256 (all).
        {
            const int bb = t >> 6, kk = t & 63;
            const int k  = rc * 64 + kk;
            const int cc = k >> 9, r = k & LMASK;
            const float* p = &g_part[(((size_t)(b0 + bb) * Cc + cc) * NBLK) * Lr + r];
            float ssum = 0.f;
            #pragma unroll
            for (int q = 0; q < NBLK; ++q) ssum += p[q * Lr];
            ssep[bb][kk] = ssum;
        }
        __syncthreads();

        #pragma unroll 8
        for (int kk = 0; kk < 64; ++kk) {
            float w = W1[(size_t)(rc * 64 + kk) * HIDN + t];
            #pragma unroll
            for (int bb = 0; bb < MBSUB; ++bb)
                acc[bb] = fmaf(ssep[bb][kk], w, acc[bb]);
        }
    }

    // Accumulate hidden pre-activations atomically.
    #pragma unroll
    for (int bb = 0; bb < MBSUB; ++bb)
        atomicAdd(&g_hacc[(b0 + bb) * HIDN + t], acc[bb]);

    // Last CTA finishes the head for all batches.
    __threadfence();
    if (t == 0) s_last = (atomicAdd(&g_ctr, 1) == NMLP - 1);
    __syncthreads();
    if (!s_last) return;

    const int wid = t >> 5, lane = t & 31;        // warp wid -> batches 2w, 2w+1
    #pragma unroll
    for (int rep = 0; rep < 2; ++rep) {
        const int bb = 2 * wid + rep;
        float sum = 0.f;
        #pragma unroll
        for (int i = 0; i < 8; ++i) {
            int col = lane + 32 * i;
            float h = __ldcg(&g_hacc[bb * HIDN + col]) + b1[col];
            sum += celu_f(h) * W2[col];
        }
        #pragma unroll
        for (int off = 16; off > 0; off >>= 1)
            sum += __shfl_down_sync(0xffffffffu, sum, off);
        if (lane == 0) out[bb] = __expf(-(sum + b2[0]));
    }
}

extern "C" void kernel_launch(void* const* d_in, const int* in_sizes, int n_in,
                              void* d_out, int out_size)
{
    const float* n      = (const float*)d_in[0];
    const float* w_self = (const float*)d_in[1];
    const float* w_nbr  = (const float*)d_in[2];
    const float* W1     = (const float*)d_in[3];
    const float* b1     = (const float*)d_in[4];
    const float* W2     = (const float*)d_in[5];
    const float* b2     = (const float*)d_in[6];
    float* out = (float*)d_out;

    const size_t smem_bytes = SMEM_FLOATS * sizeof(float);   // 104448 B
    cudaFuncSetAttribute(fused_layers_kernel,
                         cudaFuncAttributeMaxDynamicSharedMemorySize,
                         (int)smem_bytes);

    dim3 grid(NBLK, Bb, Cc);   // 1024 CTAs; actives (c==0) are bids 0..255
    fused_layers_kernel<<<grid, TPB, smem_bytes>>>(n, w_self, w_nbr, W1);

    mlp_kernel<<<dim3(NRC, MBG), 256>>>(W1, w_self, w_nbr, b1, W2, b2, out);
}